// round 13
// baseline (speedup 1.0000x reference)
#include <cuda_runtime.h>

typedef unsigned long long u64;

#define N_NODES 50000
#define N_EDGES 1000000
#define NH      1024
#define INV_E   (1.0f/1000000.0f)
#define SCAN_BLOCKS 49   // 49*1024 = 50176 >= N_NODES+1

// ---------------- scratch (device globals; no allocation allowed) ----------
__device__ __align__(16) float g_xp  [N_NODES*64];  // x@W1+b1
__device__ __align__(16) float g_h1p [N_NODES*32];  // relu(gather1(xp))@W2+b2
__device__ __align__(16) float g_h2r [N_NODES*32];  // relu(gather2(h1p))
__device__ __align__(16) float g_nf  [N_NODES*32];  // gather3(h2r)  (no /E yet)
__device__ __align__(16) float g_ehtmp[NH*32];      // edge_features@We
__device__ __align__(16) float g_eh  [NH*32];       // adj_e@ehtmp
// CSR by destination
__device__ int g_off [N_NODES+1];
__device__ int g_woff[N_NODES];
__device__ int g_bsum[SCAN_BLOCKS];
__device__ int g_boff[SCAN_BLOCKS];
__device__ __align__(8) u64 g_esw[N_EDGES];         // packed {w<<32 | src}

// ---------------- f32x2 helpers --------------------------------------------
__device__ __forceinline__ u64 dup2(float v){
    unsigned u = __float_as_uint(v); u64 r;
    asm("mov.b64 %0, {%1, %2};" : "=l"(r) : "r"(u), "r"(u));
    return r;
}
__device__ __forceinline__ void ffma2(u64 &d, u64 a, u64 b){
    asm("fma.rn.f32x2 %0, %1, %2, %0;" : "+l"(d) : "l"(a), "l"(b));
}
__device__ __forceinline__ void unpack2(u64 v, float &lo, float &hi){
    unsigned a, b;
    asm("mov.b64 {%0, %1}, %2;" : "=r"(a), "=r"(b) : "l"(v));
    lo = __uint_as_float(a); hi = __uint_as_float(b);
}

// ---------------- CSR build -------------------------------------------------
__global__ void k_count(const int* __restrict__ ei){
    int e = blockIdx.x*256 + threadIdx.x;
    if (e < N_EDGES) atomicAdd(&g_off[__ldg(ei + N_EDGES + e) + 1], 1);
}

// hierarchical scan: coalesced, multi-block
__global__ __launch_bounds__(1024) void k_scan1(){        // block sums
    int idx = blockIdx.x*1024 + threadIdx.x;
    int v = (idx <= N_NODES) ? g_off[idx] : 0;
    __shared__ int ws[32];
    #pragma unroll
    for (int o = 16; o > 0; o >>= 1) v += __shfl_down_sync(0xffffffffu, v, o);
    if ((threadIdx.x & 31) == 0) ws[threadIdx.x >> 5] = v;
    __syncthreads();
    if (threadIdx.x < 32){
        int s = ws[threadIdx.x];
        #pragma unroll
        for (int o = 16; o > 0; o >>= 1) s += __shfl_down_sync(0xffffffffu, s, o);
        if (threadIdx.x == 0) g_bsum[blockIdx.x] = s;
    }
}

__global__ __launch_bounds__(64) void k_scan2(){          // scan block sums
    __shared__ int sm[64];
    int t = threadIdx.x;
    int v = (t < SCAN_BLOCKS) ? g_bsum[t] : 0;
    sm[t] = v; __syncthreads();
    #pragma unroll
    for (int o = 1; o < 64; o <<= 1){
        int u = (t >= o) ? sm[t-o] : 0;
        __syncthreads();
        sm[t] += u;
        __syncthreads();
    }
    if (t < SCAN_BLOCKS) g_boff[t] = sm[t] - v;   // exclusive
}

__global__ __launch_bounds__(1024) void k_scan3(){        // block-local scan + offset
    __shared__ int sm[1024];
    int t = threadIdx.x;
    int idx = blockIdx.x*1024 + t;
    int v = (idx <= N_NODES) ? g_off[idx] : 0;
    sm[t] = v; __syncthreads();
    #pragma unroll
    for (int o = 1; o < 1024; o <<= 1){
        int u = (t >= o) ? sm[t-o] : 0;
        __syncthreads();
        sm[t] += u;
        __syncthreads();
    }
    if (idx <= N_NODES){
        int r = sm[t] + g_boff[blockIdx.x];
        g_off[idx] = r;
        if (idx < N_NODES) g_woff[idx] = r;
    }
}

__global__ void k_fill(const int* __restrict__ ei, const float* __restrict__ w){
    int e = blockIdx.x*256 + threadIdx.x;
    if (e >= N_EDGES) return;
    int s = __ldg(ei + e);
    int d = __ldg(ei + N_EDGES + e);
    float wt = __ldg(w + e);
    int pos = atomicAdd(&g_woff[d], 1);
    g_esw[pos] = ((u64)__float_as_uint(wt) << 32) | (unsigned)s;
}

// ---------------- GEMM1: xp = x[N,128]@W1[128,64] + b1 ---------------------
// 2 nodes x 32 outputs per thread: each weight LDS feeds 4 FFMA2.
__global__ __launch_bounds__(256) void k_gemm1(const float* __restrict__ x,
        const float* __restrict__ W, const float* __restrict__ b){
    __shared__ float Ws[128*64];
    for (int t = threadIdx.x; t < 128*64; t += 256) Ws[t] = W[t];
    __syncthreads();
    int tid  = blockIdx.x*256 + threadIdx.x;
    int pair = tid >> 1;
    int half = tid & 1;
    int n0 = pair*2, n1 = n0 + 1;
    bool v0 = n0 < N_NODES, v1 = n1 < N_NODES;
    int m0 = v0 ? n0 : 0, m1 = v1 ? n1 : 0;
    u64 accA[16], accB[16];
    const u64* bp = (const u64*)(b + half*32);
    #pragma unroll
    for (int j = 0; j < 16; j++){ accA[j] = bp[j]; accB[j] = bp[j]; }
    const float4* x0 = (const float4*)x + (size_t)m0*32;
    const float4* x1 = (const float4*)x + (size_t)m1*32;
    const ulonglong2* Ws2 = (const ulonglong2*)Ws;
    #pragma unroll 1
    for (int k4 = 0; k4 < 32; k4++){
        float4 xa = __ldg(x0 + k4);
        float4 xb = __ldg(x1 + k4);
        float ca[4] = {xa.x, xa.y, xa.z, xa.w};
        float cb[4] = {xb.x, xb.y, xb.z, xb.w};
        #pragma unroll
        for (int c = 0; c < 4; c++){
            u64 xd0 = dup2(ca[c]);
            u64 xd1 = dup2(cb[c]);
            const ulonglong2* wr = Ws2 + (k4*4 + c)*16 + half*8;
            #pragma unroll
            for (int j = 0; j < 8; j++){
                ulonglong2 wv = wr[j];
                ffma2(accA[2*j],   xd0, wv.x);
                ffma2(accA[2*j+1], xd0, wv.y);
                ffma2(accB[2*j],   xd1, wv.x);
                ffma2(accB[2*j+1], xd1, wv.y);
            }
        }
    }
    if (v0){
        u64* op = (u64*)g_xp + (size_t)n0*32 + half*16;
        #pragma unroll
        for (int j = 0; j < 16; j++) op[j] = accA[j];
    }
    if (v1){
        u64* op = (u64*)g_xp + (size_t)n1*32 + half*16;
        #pragma unroll
        for (int j = 0; j < 16; j++) op[j] = accB[j];
    }
}

// ---------------- gather1: h1p = relu(sum w*xp[src]) @ W2 + b2 -------------
__global__ __launch_bounds__(256) void k_gather1(const float* __restrict__ W2,
        const float* __restrict__ b2){
    __shared__ float Ws[64*32];
    __shared__ float bs[32];
    __shared__ float vbuf[8][64];
    for (int t = threadIdx.x; t < 64*32; t += 256) Ws[t] = W2[t];
    if (threadIdx.x < 32) bs[threadIdx.x] = b2[threadIdx.x];
    __syncthreads();
    int warp = threadIdx.x >> 5, lane = threadIdx.x & 31;
    int node = blockIdx.x*8 + warp;
    if (node >= N_NODES) return;
    int beg = __ldg(&g_off[node]), end = __ldg(&g_off[node+1]);
    const float* xp = g_xp + lane*2;
    float ax0=0.f, ay0=0.f, ax1=0.f, ay1=0.f;
    int idx = beg;
    #pragma unroll 1
    for (; idx + 4 <= end; idx += 4){
        u64 m0 = __ldg(g_esw + idx + 0);
        u64 m1 = __ldg(g_esw + idx + 1);
        u64 m2 = __ldg(g_esw + idx + 2);
        u64 m3 = __ldg(g_esw + idx + 3);
        float2 v0 = *(const float2*)(xp + (size_t)(unsigned)m0 * 64);
        float2 v1 = *(const float2*)(xp + (size_t)(unsigned)m1 * 64);
        float2 v2 = *(const float2*)(xp + (size_t)(unsigned)m2 * 64);
        float2 v3 = *(const float2*)(xp + (size_t)(unsigned)m3 * 64);
        float w0 = __uint_as_float((unsigned)(m0 >> 32));
        float w1 = __uint_as_float((unsigned)(m1 >> 32));
        float w2 = __uint_as_float((unsigned)(m2 >> 32));
        float w3 = __uint_as_float((unsigned)(m3 >> 32));
        ax0 = fmaf(w0, v0.x, ax0); ay0 = fmaf(w0, v0.y, ay0);
        ax1 = fmaf(w1, v1.x, ax1); ay1 = fmaf(w1, v1.y, ay1);
        ax0 = fmaf(w2, v2.x, ax0); ay0 = fmaf(w2, v2.y, ay0);
        ax1 = fmaf(w3, v3.x, ax1); ay1 = fmaf(w3, v3.y, ay1);
    }
    #pragma unroll 1
    for (; idx < end; idx++){
        u64 m = __ldg(g_esw + idx);
        float2 v = *(const float2*)(xp + (size_t)(unsigned)m * 64);
        float w = __uint_as_float((unsigned)(m >> 32));
        ax0 = fmaf(w, v.x, ax0); ay0 = fmaf(w, v.y, ay0);
    }
    vbuf[warp][lane*2]   = fmaxf(ax0 + ax1, 0.f);
    vbuf[warp][lane*2+1] = fmaxf(ay0 + ay1, 0.f);
    __syncwarp();
    float o = bs[lane];
    #pragma unroll
    for (int k = 0; k < 64; k++) o = fmaf(vbuf[warp][k], Ws[k*32 + lane], o);
    g_h1p[(size_t)node*32 + lane] = o;
}

// ---------------- gather2: h2r = relu(sum w*h1p[src]) ----------------------
__global__ __launch_bounds__(256) void k_gather2(){
    int warp = threadIdx.x >> 5, lane = threadIdx.x & 31;
    int node = blockIdx.x*8 + warp;
    if (node >= N_NODES) return;
    int beg = __ldg(&g_off[node]), end = __ldg(&g_off[node+1]);
    const float* hp = g_h1p + lane;
    float a0=0.f, a1=0.f, a2=0.f, a3=0.f;
    int idx = beg;
    #pragma unroll 1
    for (; idx + 4 <= end; idx += 4){
        u64 m0 = __ldg(g_esw + idx + 0);
        u64 m1 = __ldg(g_esw + idx + 1);
        u64 m2 = __ldg(g_esw + idx + 2);
        u64 m3 = __ldg(g_esw + idx + 3);
        float v0 = __ldg(hp + (size_t)(unsigned)m0 * 32);
        float v1 = __ldg(hp + (size_t)(unsigned)m1 * 32);
        float v2 = __ldg(hp + (size_t)(unsigned)m2 * 32);
        float v3 = __ldg(hp + (size_t)(unsigned)m3 * 32);
        a0 = fmaf(__uint_as_float((unsigned)(m0 >> 32)), v0, a0);
        a1 = fmaf(__uint_as_float((unsigned)(m1 >> 32)), v1, a1);
        a2 = fmaf(__uint_as_float((unsigned)(m2 >> 32)), v2, a2);
        a3 = fmaf(__uint_as_float((unsigned)(m3 >> 32)), v3, a3);
    }
    #pragma unroll 1
    for (; idx < end; idx++){
        u64 m = __ldg(g_esw + idx);
        a0 = fmaf(__uint_as_float((unsigned)(m >> 32)),
                  __ldg(hp + (size_t)(unsigned)m * 32), a0);
    }
    g_h2r[(size_t)node*32 + lane] = fmaxf((a0 + a1) + (a2 + a3), 0.f);
}

// ---------------- gather3: nf = sum h2r[src] (unweighted) ------------------
__global__ __launch_bounds__(256) void k_gather3(){
    int warp = threadIdx.x >> 5, lane = threadIdx.x & 31;
    int node = blockIdx.x*8 + warp;
    if (node >= N_NODES) return;
    int beg = __ldg(&g_off[node]), end = __ldg(&g_off[node+1]);
    const float* hp = g_h2r + lane;
    float a0=0.f, a1=0.f, a2=0.f, a3=0.f;
    int idx = beg;
    #pragma unroll 1
    for (; idx + 4 <= end; idx += 4){
        u64 m0 = __ldg(g_esw + idx + 0);
        u64 m1 = __ldg(g_esw + idx + 1);
        u64 m2 = __ldg(g_esw + idx + 2);
        u64 m3 = __ldg(g_esw + idx + 3);
        a0 += __ldg(hp + (size_t)(unsigned)m0 * 32);
        a1 += __ldg(hp + (size_t)(unsigned)m1 * 32);
        a2 += __ldg(hp + (size_t)(unsigned)m2 * 32);
        a3 += __ldg(hp + (size_t)(unsigned)m3 * 32);
    }
    #pragma unroll 1
    for (; idx < end; idx++){
        u64 m = __ldg(g_esw + idx);
        a0 += __ldg(hp + (size_t)(unsigned)m * 32);
    }
    g_nf[(size_t)node*32 + lane] = (a0 + a1) + (a2 + a3);
}

// ---------------- ehtmp = edge_features[1024,64]@We[64,32] -----------------
__global__ __launch_bounds__(128) void k_ew1(const float* __restrict__ ef,
        const float* __restrict__ We){
    __shared__ float Ws[64*32];
    for (int t = threadIdx.x; t < 64*32; t += 128) Ws[t] = We[t];
    __syncthreads();
    int i = blockIdx.x*128 + threadIdx.x;     // exactly 1024 threads total
    u64 acc[16] = {};
    const float4* er = (const float4*)ef + (size_t)i*16;
    const ulonglong2* Ws2 = (const ulonglong2*)Ws;
    #pragma unroll 1
    for (int k4 = 0; k4 < 16; k4++){
        float4 ev = __ldg(er + k4);
        float ec[4] = {ev.x, ev.y, ev.z, ev.w};
        #pragma unroll
        for (int c = 0; c < 4; c++){
            u64 ed = dup2(ec[c]);
            const ulonglong2* wr = Ws2 + (k4*4 + c)*8;
            #pragma unroll
            for (int j = 0; j < 8; j++){
                ulonglong2 wv = wr[j];
                ffma2(acc[2*j],   ed, wv.x);
                ffma2(acc[2*j+1], ed, wv.y);
            }
        }
    }
    u64* op = (u64*)g_ehtmp + (size_t)i*16;
    #pragma unroll
    for (int j = 0; j < 16; j++) op[j] = acc[j];
}

// ---------------- eh = adj_e[1024,1024]@ehtmp[1024,32] ---------------------
__global__ __launch_bounds__(128) void k_ew2(const float* __restrict__ adj){
    __shared__ float Ts[64*32];
    int i = blockIdx.x*128 + threadIdx.x;
    u64 acc[16] = {};
    const ulonglong2* Ts2 = (const ulonglong2*)Ts;
    for (int kt = 0; kt < 16; kt++){
        __syncthreads();
        for (int t = threadIdx.x; t < 2048; t += 128) Ts[t] = g_ehtmp[kt*2048 + t];
        __syncthreads();
        const float4* ar = (const float4*)adj + (size_t)i*256 + kt*16;
        #pragma unroll 1
        for (int k4 = 0; k4 < 16; k4++){
            float4 av = __ldg(ar + k4);
            float ac[4] = {av.x, av.y, av.z, av.w};
            #pragma unroll
            for (int c = 0; c < 4; c++){
                u64 ad = dup2(ac[c]);
                const ulonglong2* wr = Ts2 + (k4*4 + c)*8;
                #pragma unroll
                for (int j = 0; j < 8; j++){
                    ulonglong2 wv = wr[j];
                    ffma2(acc[2*j],   ad, wv.x);
                    ffma2(acc[2*j+1], ad, wv.y);
                }
            }
        }
    }
    u64* op = (u64*)g_eh + (size_t)i*16;
    #pragma unroll
    for (int j = 0; j < 16; j++) op[j] = acc[j];
}

// ---------------- fused: shared=relu(nf/E@Wn + T@eh + bg) -> classifier ----
__global__ __launch_bounds__(128) void k_final(const float* __restrict__ T,
        const float* __restrict__ Wn,  const float* __restrict__ bg,
        const float* __restrict__ Wc1, const float* __restrict__ bc1,
        const float* __restrict__ Wc2, const float* __restrict__ bc2,
        float* __restrict__ out){
    __shared__ float ehs[2048];
    __shared__ float Wns[1024];
    __shared__ float Wc1s[1024];
    __shared__ float Wc2s[64];
    __shared__ float bgs[32];
    __shared__ float bc1s[32];
    __shared__ float bc2s[2];
    for (int t = threadIdx.x; t < 1024; t += 128){ Wns[t] = Wn[t]; Wc1s[t] = Wc1[t]; }
    if (threadIdx.x < 64) Wc2s[threadIdx.x] = Wc2[threadIdx.x];
    if (threadIdx.x < 32){ bgs[threadIdx.x] = bg[threadIdx.x]; bc1s[threadIdx.x] = bc1[threadIdx.x]; }
    if (threadIdx.x < 2)  bc2s[threadIdx.x] = bc2[threadIdx.x];
    __syncthreads();

    int i  = blockIdx.x*128 + threadIdx.x;
    int ii = i < N_NODES ? i : 0;

    u64 acc[16];
    const u64* bgp = (const u64*)bgs;
    #pragma unroll
    for (int j = 0; j < 16; j++) acc[j] = bgp[j];

    const ulonglong2* ehs2 = (const ulonglong2*)ehs;
    for (int kt = 0; kt < 16; kt++){
        __syncthreads();
        for (int t = threadIdx.x; t < 2048; t += 128) ehs[t] = g_eh[kt*2048 + t];
        __syncthreads();
        const float4* tr = (const float4*)T + (size_t)ii*256 + kt*16;
        #pragma unroll 1
        for (int k4 = 0; k4 < 16; k4++){
            float4 tv = __ldg(tr + k4);
            float tc[4] = {tv.x, tv.y, tv.z, tv.w};
            #pragma unroll
            for (int c = 0; c < 4; c++){
                u64 td = dup2(tc[c]);
                const ulonglong2* wr = ehs2 + (k4*4 + c)*8;
                #pragma unroll
                for (int j = 0; j < 8; j++){
                    ulonglong2 wv = wr[j];
                    ffma2(acc[2*j],   td, wv.x);
                    ffma2(acc[2*j+1], td, wv.y);
                }
            }
        }
    }

    // nf/E @ Wn accumulated into the same acc
    const float4* nr = (const float4*)g_nf + (size_t)ii*8;
    const ulonglong2* Wns2 = (const ulonglong2*)Wns;
    #pragma unroll 1
    for (int k4 = 0; k4 < 8; k4++){
        float4 nv = nr[k4];
        float nc[4] = {nv.x*INV_E, nv.y*INV_E, nv.z*INV_E, nv.w*INV_E};
        #pragma unroll
        for (int c = 0; c < 4; c++){
            u64 nd = dup2(nc[c]);
            const ulonglong2* wr = Wns2 + (k4*4 + c)*8;
            #pragma unroll
            for (int j = 0; j < 8; j++){
                ulonglong2 wv = wr[j];
                ffma2(acc[2*j],   nd, wv.x);
                ffma2(acc[2*j+1], nd, wv.y);
            }
        }
    }

    float s[32];
    #pragma unroll
    for (int j = 0; j < 16; j++){
        float lo, hi; unpack2(acc[j], lo, hi);
        s[2*j] = fmaxf(lo, 0.f); s[2*j+1] = fmaxf(hi, 0.f);
    }

    // classifier layer1: c = relu(s@Wc1 + bc1)
    u64 cacc[16];
    const u64* bcp = (const u64*)bc1s;
    #pragma unroll
    for (int j = 0; j < 16; j++) cacc[j] = bcp[j];
    const ulonglong2* Wc1s2 = (const ulonglong2*)Wc1s;
    #pragma unroll
    for (int k = 0; k < 32; k++){
        u64 sd = dup2(s[k]);
        const ulonglong2* wr = Wc1s2 + k*8;
        #pragma unroll
        for (int j = 0; j < 8; j++){
            ulonglong2 wv = wr[j];
            ffma2(cacc[2*j],   sd, wv.x);
            ffma2(cacc[2*j+1], sd, wv.y);
        }
    }

    // logits + softmax (2 classes)
    float l0 = bc2s[0], l1 = bc2s[1];
    #pragma unroll
    for (int k = 0; k < 16; k++){
        float lo, hi; unpack2(cacc[k], lo, hi);
        lo = fmaxf(lo, 0.f); hi = fmaxf(hi, 0.f);
        l0 += lo*Wc2s[4*k]   + hi*Wc2s[4*k+2];
        l1 += lo*Wc2s[4*k+1] + hi*Wc2s[4*k+3];
    }
    float m  = fmaxf(l0, l1);
    float e0 = expf(l0 - m), e1 = expf(l1 - m);
    float inv = 1.f/(e0 + e1);
    if (i < N_NODES){
        reinterpret_cast<float2*>(out)[i] = make_float2(e0*inv, e1*inv);
    }
}

// ---------------------------------------------------------------------------
extern "C" void kernel_launch(void* const* d_in, const int* in_sizes, int n_in,
                              void* d_out, int out_size){
    const float* x   = (const float*)d_in[0];
    const int*   ei  = (const int*)d_in[1];        // int32 (JAX downcasts int64)
    const float* ew  = (const float*)d_in[2];
    const float* ef  = (const float*)d_in[3];
    const float* adj = (const float*)d_in[4];
    const float* T   = (const float*)d_in[5];
    const float* W1  = (const float*)d_in[6];
    const float* b1  = (const float*)d_in[7];
    const float* W2  = (const float*)d_in[8];
    const float* b2  = (const float*)d_in[9];
    const float* Wn  = (const float*)d_in[10];
    const float* We  = (const float*)d_in[11];
    const float* bg  = (const float*)d_in[12];
    const float* Wc1 = (const float*)d_in[13];
    const float* bc1 = (const float*)d_in[14];
    const float* Wc2 = (const float*)d_in[15];
    const float* bc2 = (const float*)d_in[16];
    float* out = (float*)d_out;

    void* poff = nullptr;
    cudaGetSymbolAddress(&poff, g_off);

    // side stream + events, created once on the first (non-captured) call
    static cudaStream_t s2 = nullptr;
    static cudaEvent_t ev0 = nullptr, ev1 = nullptr, ev2 = nullptr;
    if (!s2){
        cudaStreamCreateWithFlags(&s2, cudaStreamNonBlocking);
        cudaEventCreateWithFlags(&ev0, cudaEventDisableTiming);
        cudaEventCreateWithFlags(&ev1, cudaEventDisableTiming);
        cudaEventCreateWithFlags(&ev2, cudaEventDisableTiming);
    }

    // fork: dense chain on s2, overlapped with CSR build on default stream
    cudaEventRecord(ev0, 0);
    cudaStreamWaitEvent(s2, ev0, 0);
    k_gemm1<<<196, 256, 0, s2>>>(x, W1, b1);
    cudaEventRecord(ev1, s2);
    k_ew1<<<8, 128, 0, s2>>>(ef, We);
    k_ew2<<<8, 128, 0, s2>>>(adj);
    cudaEventRecord(ev2, s2);

    // CSR build (default stream)
    cudaMemsetAsync(poff, 0, (N_NODES+1)*sizeof(int));
    k_count<<<3907, 256>>>(ei);
    k_scan1<<<SCAN_BLOCKS, 1024>>>();
    k_scan2<<<1, 64>>>();
    k_scan3<<<SCAN_BLOCKS, 1024>>>();
    k_fill<<<3907, 256>>>(ei, ew);

    // join gemm1 before gather1
    cudaStreamWaitEvent(0, ev1, 0);
    k_gather1<<<6250, 256>>>(W2, b2);
    k_gather2<<<6250, 256>>>();
    k_gather3<<<6250, 256>>>();

    // join ew2 before final
    cudaStreamWaitEvent(0, ev2, 0);
    k_final<<<391, 128>>>(T, Wn, bg, Wc1, bc1, Wc2, bc2, out);
}

// round 14
// speedup vs baseline: 1.0082x; 1.0082x over previous
#include <cuda_runtime.h>

typedef unsigned long long u64;

#define N_NODES 50000
#define N_EDGES 1000000
#define NH      1024
#define INV_E   (1.0f/1000000.0f)
#define SCAN_BLOCKS 49   // 49*1024 = 50176 >= N_NODES+1

// ---------------- scratch (device globals; no allocation allowed) ----------
__device__ __align__(16) float g_xp  [N_NODES*64];  // x@W1+b1
__device__ __align__(16) float g_h1p [N_NODES*32];  // relu(gather1(xp))@W2+b2
__device__ __align__(16) float g_h2r [N_NODES*32];  // relu(gather2(h1p))
__device__ __align__(16) float g_nf  [N_NODES*32];  // gather3(h2r)  (no /E yet)
__device__ __align__(16) float g_ehtmp[NH*32];      // edge_features@We
__device__ __align__(16) float g_eh  [NH*32];       // adj_e@ehtmp
// CSR by destination
__device__ int g_off [N_NODES+1];
__device__ int g_woff[N_NODES];
__device__ int g_bsum[SCAN_BLOCKS];
__device__ int g_boff[SCAN_BLOCKS];
__device__ __align__(8) u64 g_esw[N_EDGES];         // packed {w<<32 | src}

// ---------------- f32x2 helpers --------------------------------------------
__device__ __forceinline__ u64 dup2(float v){
    unsigned u = __float_as_uint(v); u64 r;
    asm("mov.b64 %0, {%1, %2};" : "=l"(r) : "r"(u), "r"(u));
    return r;
}
__device__ __forceinline__ void ffma2(u64 &d, u64 a, u64 b){
    asm("fma.rn.f32x2 %0, %1, %2, %0;" : "+l"(d) : "l"(a), "l"(b));
}
__device__ __forceinline__ void unpack2(u64 v, float &lo, float &hi){
    unsigned a, b;
    asm("mov.b64 {%0, %1}, %2;" : "=r"(a), "=r"(b) : "l"(v));
    lo = __uint_as_float(a); hi = __uint_as_float(b);
}

// ---------------- CSR build -------------------------------------------------
__global__ void k_count(const int* __restrict__ ei){
    int e = blockIdx.x*256 + threadIdx.x;
    if (e < N_EDGES) atomicAdd(&g_off[__ldg(ei + N_EDGES + e) + 1], 1);
}

// hierarchical scan: coalesced, multi-block
__global__ __launch_bounds__(1024) void k_scan1(){        // block sums
    int idx = blockIdx.x*1024 + threadIdx.x;
    int v = (idx <= N_NODES) ? g_off[idx] : 0;
    __shared__ int ws[32];
    #pragma unroll
    for (int o = 16; o > 0; o >>= 1) v += __shfl_down_sync(0xffffffffu, v, o);
    if ((threadIdx.x & 31) == 0) ws[threadIdx.x >> 5] = v;
    __syncthreads();
    if (threadIdx.x < 32){
        int s = ws[threadIdx.x];
        #pragma unroll
        for (int o = 16; o > 0; o >>= 1) s += __shfl_down_sync(0xffffffffu, s, o);
        if (threadIdx.x == 0) g_bsum[blockIdx.x] = s;
    }
}

__global__ __launch_bounds__(64) void k_scan2(){          // scan block sums
    __shared__ int sm[64];
    int t = threadIdx.x;
    int v = (t < SCAN_BLOCKS) ? g_bsum[t] : 0;
    sm[t] = v; __syncthreads();
    #pragma unroll
    for (int o = 1; o < 64; o <<= 1){
        int u = (t >= o) ? sm[t-o] : 0;
        __syncthreads();
        sm[t] += u;
        __syncthreads();
    }
    if (t < SCAN_BLOCKS) g_boff[t] = sm[t] - v;   // exclusive
}

__global__ __launch_bounds__(1024) void k_scan3(){        // block-local scan + offset
    __shared__ int sm[1024];
    int t = threadIdx.x;
    int idx = blockIdx.x*1024 + t;
    int v = (idx <= N_NODES) ? g_off[idx] : 0;
    sm[t] = v; __syncthreads();
    #pragma unroll
    for (int o = 1; o < 1024; o <<= 1){
        int u = (t >= o) ? sm[t-o] : 0;
        __syncthreads();
        sm[t] += u;
        __syncthreads();
    }
    if (idx <= N_NODES){
        int r = sm[t] + g_boff[blockIdx.x];
        g_off[idx] = r;
        if (idx < N_NODES) g_woff[idx] = r;
    }
}

__global__ void k_fill(const int* __restrict__ ei, const float* __restrict__ w){
    int e = blockIdx.x*256 + threadIdx.x;
    if (e >= N_EDGES) return;
    int s = __ldg(ei + e);
    int d = __ldg(ei + N_EDGES + e);
    float wt = __ldg(w + e);
    int pos = atomicAdd(&g_woff[d], 1);
    g_esw[pos] = ((u64)__float_as_uint(wt) << 32) | (unsigned)s;
}

// ---------------- GEMM1: xp = x[N,128]@W1[128,64] + b1 ---------------------
// 2 nodes x 32 outputs per thread: each weight LDS feeds 4 FFMA2.
__global__ __launch_bounds__(256) void k_gemm1(const float* __restrict__ x,
        const float* __restrict__ W, const float* __restrict__ b){
    __shared__ float Ws[128*64];
    for (int t = threadIdx.x; t < 128*64; t += 256) Ws[t] = W[t];
    __syncthreads();
    int tid  = blockIdx.x*256 + threadIdx.x;
    int pair = tid >> 1;
    int half = tid & 1;
    int n0 = pair*2, n1 = n0 + 1;
    bool v0 = n0 < N_NODES, v1 = n1 < N_NODES;
    int m0 = v0 ? n0 : 0, m1 = v1 ? n1 : 0;
    u64 accA[16], accB[16];
    const u64* bp = (const u64*)(b + half*32);
    #pragma unroll
    for (int j = 0; j < 16; j++){ accA[j] = bp[j]; accB[j] = bp[j]; }
    const float4* x0 = (const float4*)x + (size_t)m0*32;
    const float4* x1 = (const float4*)x + (size_t)m1*32;
    const ulonglong2* Ws2 = (const ulonglong2*)Ws;
    #pragma unroll 1
    for (int k4 = 0; k4 < 32; k4++){
        float4 xa = __ldg(x0 + k4);
        float4 xb = __ldg(x1 + k4);
        float ca[4] = {xa.x, xa.y, xa.z, xa.w};
        float cb[4] = {xb.x, xb.y, xb.z, xb.w};
        #pragma unroll
        for (int c = 0; c < 4; c++){
            u64 xd0 = dup2(ca[c]);
            u64 xd1 = dup2(cb[c]);
            const ulonglong2* wr = Ws2 + (k4*4 + c)*16 + half*8;
            #pragma unroll
            for (int j = 0; j < 8; j++){
                ulonglong2 wv = wr[j];
                ffma2(accA[2*j],   xd0, wv.x);
                ffma2(accA[2*j+1], xd0, wv.y);
                ffma2(accB[2*j],   xd1, wv.x);
                ffma2(accB[2*j+1], xd1, wv.y);
            }
        }
    }
    if (v0){
        u64* op = (u64*)g_xp + (size_t)n0*32 + half*16;
        #pragma unroll
        for (int j = 0; j < 16; j++) op[j] = accA[j];
    }
    if (v1){
        u64* op = (u64*)g_xp + (size_t)n1*32 + half*16;
        #pragma unroll
        for (int j = 0; j < 16; j++) op[j] = accB[j];
    }
}

// ---------------- gather1: h1p = relu(sum w*xp[src]) @ W2 + b2 -------------
__global__ __launch_bounds__(256) void k_gather1(const float* __restrict__ W2,
        const float* __restrict__ b2){
    __shared__ float Ws[64*32];
    __shared__ float bs[32];
    __shared__ float vbuf[8][64];
    for (int t = threadIdx.x; t < 64*32; t += 256) Ws[t] = W2[t];
    if (threadIdx.x < 32) bs[threadIdx.x] = b2[threadIdx.x];
    __syncthreads();
    int warp = threadIdx.x >> 5, lane = threadIdx.x & 31;
    int node = blockIdx.x*8 + warp;
    if (node >= N_NODES) return;
    int beg = __ldg(&g_off[node]), end = __ldg(&g_off[node+1]);
    const float* xp = g_xp + lane*2;
    float ax0=0.f, ay0=0.f, ax1=0.f, ay1=0.f;
    int idx = beg;
    #pragma unroll 1
    for (; idx + 4 <= end; idx += 4){
        u64 m0 = __ldg(g_esw + idx + 0);
        u64 m1 = __ldg(g_esw + idx + 1);
        u64 m2 = __ldg(g_esw + idx + 2);
        u64 m3 = __ldg(g_esw + idx + 3);
        float2 v0 = *(const float2*)(xp + (size_t)(unsigned)m0 * 64);
        float2 v1 = *(const float2*)(xp + (size_t)(unsigned)m1 * 64);
        float2 v2 = *(const float2*)(xp + (size_t)(unsigned)m2 * 64);
        float2 v3 = *(const float2*)(xp + (size_t)(unsigned)m3 * 64);
        float w0 = __uint_as_float((unsigned)(m0 >> 32));
        float w1 = __uint_as_float((unsigned)(m1 >> 32));
        float w2 = __uint_as_float((unsigned)(m2 >> 32));
        float w3 = __uint_as_float((unsigned)(m3 >> 32));
        ax0 = fmaf(w0, v0.x, ax0); ay0 = fmaf(w0, v0.y, ay0);
        ax1 = fmaf(w1, v1.x, ax1); ay1 = fmaf(w1, v1.y, ay1);
        ax0 = fmaf(w2, v2.x, ax0); ay0 = fmaf(w2, v2.y, ay0);
        ax1 = fmaf(w3, v3.x, ax1); ay1 = fmaf(w3, v3.y, ay1);
    }
    #pragma unroll 1
    for (; idx < end; idx++){
        u64 m = __ldg(g_esw + idx);
        float2 v = *(const float2*)(xp + (size_t)(unsigned)m * 64);
        float w = __uint_as_float((unsigned)(m >> 32));
        ax0 = fmaf(w, v.x, ax0); ay0 = fmaf(w, v.y, ay0);
    }
    vbuf[warp][lane*2]   = fmaxf(ax0 + ax1, 0.f);
    vbuf[warp][lane*2+1] = fmaxf(ay0 + ay1, 0.f);
    __syncwarp();
    float o = bs[lane];
    #pragma unroll
    for (int k = 0; k < 64; k++) o = fmaf(vbuf[warp][k], Ws[k*32 + lane], o);
    g_h1p[(size_t)node*32 + lane] = o;
}

// ---------------- gather2: h2r = relu(sum w*h1p[src]) ----------------------
__global__ __launch_bounds__(256) void k_gather2(){
    int warp = threadIdx.x >> 5, lane = threadIdx.x & 31;
    int node = blockIdx.x*8 + warp;
    if (node >= N_NODES) return;
    int beg = __ldg(&g_off[node]), end = __ldg(&g_off[node+1]);
    const float* hp = g_h1p + lane;
    float a0=0.f, a1=0.f, a2=0.f, a3=0.f;
    int idx = beg;
    #pragma unroll 1
    for (; idx + 4 <= end; idx += 4){
        u64 m0 = __ldg(g_esw + idx + 0);
        u64 m1 = __ldg(g_esw + idx + 1);
        u64 m2 = __ldg(g_esw + idx + 2);
        u64 m3 = __ldg(g_esw + idx + 3);
        float v0 = __ldg(hp + (size_t)(unsigned)m0 * 32);
        float v1 = __ldg(hp + (size_t)(unsigned)m1 * 32);
        float v2 = __ldg(hp + (size_t)(unsigned)m2 * 32);
        float v3 = __ldg(hp + (size_t)(unsigned)m3 * 32);
        a0 = fmaf(__uint_as_float((unsigned)(m0 >> 32)), v0, a0);
        a1 = fmaf(__uint_as_float((unsigned)(m1 >> 32)), v1, a1);
        a2 = fmaf(__uint_as_float((unsigned)(m2 >> 32)), v2, a2);
        a3 = fmaf(__uint_as_float((unsigned)(m3 >> 32)), v3, a3);
    }
    #pragma unroll 1
    for (; idx < end; idx++){
        u64 m = __ldg(g_esw + idx);
        a0 = fmaf(__uint_as_float((unsigned)(m >> 32)),
                  __ldg(hp + (size_t)(unsigned)m * 32), a0);
    }
    g_h2r[(size_t)node*32 + lane] = fmaxf((a0 + a1) + (a2 + a3), 0.f);
}

// ---------------- gather3: nf = sum h2r[src] (unweighted) ------------------
__global__ __launch_bounds__(256) void k_gather3(){
    int warp = threadIdx.x >> 5, lane = threadIdx.x & 31;
    int node = blockIdx.x*8 + warp;
    if (node >= N_NODES) return;
    int beg = __ldg(&g_off[node]), end = __ldg(&g_off[node+1]);
    const float* hp = g_h2r + lane;
    float a0=0.f, a1=0.f, a2=0.f, a3=0.f;
    int idx = beg;
    #pragma unroll 1
    for (; idx + 4 <= end; idx += 4){
        u64 m0 = __ldg(g_esw + idx + 0);
        u64 m1 = __ldg(g_esw + idx + 1);
        u64 m2 = __ldg(g_esw + idx + 2);
        u64 m3 = __ldg(g_esw + idx + 3);
        a0 += __ldg(hp + (size_t)(unsigned)m0 * 32);
        a1 += __ldg(hp + (size_t)(unsigned)m1 * 32);
        a2 += __ldg(hp + (size_t)(unsigned)m2 * 32);
        a3 += __ldg(hp + (size_t)(unsigned)m3 * 32);
    }
    #pragma unroll 1
    for (; idx < end; idx++){
        u64 m = __ldg(g_esw + idx);
        a0 += __ldg(hp + (size_t)(unsigned)m * 32);
    }
    g_nf[(size_t)node*32 + lane] = (a0 + a1) + (a2 + a3);
}

// ---------------- ehtmp = edge_features[1024,64]@We[64,32] -----------------
__global__ __launch_bounds__(128) void k_ew1(const float* __restrict__ ef,
        const float* __restrict__ We){
    __shared__ float Ws[64*32];
    for (int t = threadIdx.x; t < 64*32; t += 128) Ws[t] = We[t];
    __syncthreads();
    int i = blockIdx.x*128 + threadIdx.x;     // exactly 1024 threads total
    u64 acc[16] = {};
    const float4* er = (const float4*)ef + (size_t)i*16;
    const ulonglong2* Ws2 = (const ulonglong2*)Ws;
    #pragma unroll 1
    for (int k4 = 0; k4 < 16; k4++){
        float4 ev = __ldg(er + k4);
        float ec[4] = {ev.x, ev.y, ev.z, ev.w};
        #pragma unroll
        for (int c = 0; c < 4; c++){
            u64 ed = dup2(ec[c]);
            const ulonglong2* wr = Ws2 + (k4*4 + c)*8;
            #pragma unroll
            for (int j = 0; j < 8; j++){
                ulonglong2 wv = wr[j];
                ffma2(acc[2*j],   ed, wv.x);
                ffma2(acc[2*j+1], ed, wv.y);
            }
        }
    }
    u64* op = (u64*)g_ehtmp + (size_t)i*16;
    #pragma unroll
    for (int j = 0; j < 16; j++) op[j] = acc[j];
}

// ---------------- eh = adj_e[1024,1024]@ehtmp[1024,32] ---------------------
__global__ __launch_bounds__(128) void k_ew2(const float* __restrict__ adj){
    __shared__ float Ts[64*32];
    int i = blockIdx.x*128 + threadIdx.x;
    u64 acc[16] = {};
    const ulonglong2* Ts2 = (const ulonglong2*)Ts;
    for (int kt = 0; kt < 16; kt++){
        __syncthreads();
        for (int t = threadIdx.x; t < 2048; t += 128) Ts[t] = g_ehtmp[kt*2048 + t];
        __syncthreads();
        const float4* ar = (const float4*)adj + (size_t)i*256 + kt*16;
        #pragma unroll 1
        for (int k4 = 0; k4 < 16; k4++){
            float4 av = __ldg(ar + k4);
            float ac[4] = {av.x, av.y, av.z, av.w};
            #pragma unroll
            for (int c = 0; c < 4; c++){
                u64 ad = dup2(ac[c]);
                const ulonglong2* wr = Ts2 + (k4*4 + c)*8;
                #pragma unroll
                for (int j = 0; j < 8; j++){
                    ulonglong2 wv = wr[j];
                    ffma2(acc[2*j],   ad, wv.x);
                    ffma2(acc[2*j+1], ad, wv.y);
                }
            }
        }
    }
    u64* op = (u64*)g_eh + (size_t)i*16;
    #pragma unroll
    for (int j = 0; j < 16; j++) op[j] = acc[j];
}

// ---------------- fused: shared=relu(nf/E@Wn + T@eh + bg) -> classifier ----
__global__ __launch_bounds__(128) void k_final(const float* __restrict__ T,
        const float* __restrict__ Wn,  const float* __restrict__ bg,
        const float* __restrict__ Wc1, const float* __restrict__ bc1,
        const float* __restrict__ Wc2, const float* __restrict__ bc2,
        float* __restrict__ out){
    __shared__ float ehs[2048];
    __shared__ float Wns[1024];
    __shared__ float Wc1s[1024];
    __shared__ float Wc2s[64];
    __shared__ float bgs[32];
    __shared__ float bc1s[32];
    __shared__ float bc2s[2];
    for (int t = threadIdx.x; t < 1024; t += 128){ Wns[t] = Wn[t]; Wc1s[t] = Wc1[t]; }
    if (threadIdx.x < 64) Wc2s[threadIdx.x] = Wc2[threadIdx.x];
    if (threadIdx.x < 32){ bgs[threadIdx.x] = bg[threadIdx.x]; bc1s[threadIdx.x] = bc1[threadIdx.x]; }
    if (threadIdx.x < 2)  bc2s[threadIdx.x] = bc2[threadIdx.x];
    __syncthreads();

    int i  = blockIdx.x*128 + threadIdx.x;
    int ii = i < N_NODES ? i : 0;

    u64 acc[16];
    const u64* bgp = (const u64*)bgs;
    #pragma unroll
    for (int j = 0; j < 16; j++) acc[j] = bgp[j];

    const ulonglong2* ehs2 = (const ulonglong2*)ehs;
    for (int kt = 0; kt < 16; kt++){
        __syncthreads();
        for (int t = threadIdx.x; t < 2048; t += 128) ehs[t] = g_eh[kt*2048 + t];
        __syncthreads();
        const float4* tr = (const float4*)T + (size_t)ii*256 + kt*16;
        #pragma unroll 1
        for (int k4 = 0; k4 < 16; k4++){
            float4 tv = __ldg(tr + k4);
            float tc[4] = {tv.x, tv.y, tv.z, tv.w};
            #pragma unroll
            for (int c = 0; c < 4; c++){
                u64 td = dup2(tc[c]);
                const ulonglong2* wr = ehs2 + (k4*4 + c)*8;
                #pragma unroll
                for (int j = 0; j < 8; j++){
                    ulonglong2 wv = wr[j];
                    ffma2(acc[2*j],   td, wv.x);
                    ffma2(acc[2*j+1], td, wv.y);
                }
            }
        }
    }

    // nf/E @ Wn accumulated into the same acc
    const float4* nr = (const float4*)g_nf + (size_t)ii*8;
    const ulonglong2* Wns2 = (const ulonglong2*)Wns;
    #pragma unroll 1
    for (int k4 = 0; k4 < 8; k4++){
        float4 nv = nr[k4];
        float nc[4] = {nv.x*INV_E, nv.y*INV_E, nv.z*INV_E, nv.w*INV_E};
        #pragma unroll
        for (int c = 0; c < 4; c++){
            u64 nd = dup2(nc[c]);
            const ulonglong2* wr = Wns2 + (k4*4 + c)*8;
            #pragma unroll
            for (int j = 0; j < 8; j++){
                ulonglong2 wv = wr[j];
                ffma2(acc[2*j],   nd, wv.x);
                ffma2(acc[2*j+1], nd, wv.y);
            }
        }
    }

    float s[32];
    #pragma unroll
    for (int j = 0; j < 16; j++){
        float lo, hi; unpack2(acc[j], lo, hi);
        s[2*j] = fmaxf(lo, 0.f); s[2*j+1] = fmaxf(hi, 0.f);
    }

    // classifier layer1: c = relu(s@Wc1 + bc1)
    u64 cacc[16];
    const u64* bcp = (const u64*)bc1s;
    #pragma unroll
    for (int j = 0; j < 16; j++) cacc[j] = bcp[j];
    const ulonglong2* Wc1s2 = (const ulonglong2*)Wc1s;
    #pragma unroll
    for (int k = 0; k < 32; k++){
        u64 sd = dup2(s[k]);
        const ulonglong2* wr = Wc1s2 + k*8;
        #pragma unroll
        for (int j = 0; j < 8; j++){
            ulonglong2 wv = wr[j];
            ffma2(cacc[2*j],   sd, wv.x);
            ffma2(cacc[2*j+1], sd, wv.y);
        }
    }

    // logits + softmax (2 classes)
    float l0 = bc2s[0], l1 = bc2s[1];
    #pragma unroll
    for (int k = 0; k < 16; k++){
        float lo, hi; unpack2(cacc[k], lo, hi);
        lo = fmaxf(lo, 0.f); hi = fmaxf(hi, 0.f);
        l0 += lo*Wc2s[4*k]   + hi*Wc2s[4*k+2];
        l1 += lo*Wc2s[4*k+1] + hi*Wc2s[4*k+3];
    }
    float m  = fmaxf(l0, l1);
    float e0 = expf(l0 - m), e1 = expf(l1 - m);
    float inv = 1.f/(e0 + e1);
    if (i < N_NODES){
        reinterpret_cast<float2*>(out)[i] = make_float2(e0*inv, e1*inv);
    }
}

// ---------------------------------------------------------------------------
extern "C" void kernel_launch(void* const* d_in, const int* in_sizes, int n_in,
                              void* d_out, int out_size){
    const float* x   = (const float*)d_in[0];
    const int*   ei  = (const int*)d_in[1];        // int32 (JAX downcasts int64)
    const float* ew  = (const float*)d_in[2];
    const float* ef  = (const float*)d_in[3];
    const float* adj = (const float*)d_in[4];
    const float* T   = (const float*)d_in[5];
    const float* W1  = (const float*)d_in[6];
    const float* b1  = (const float*)d_in[7];
    const float* W2  = (const float*)d_in[8];
    const float* b2  = (const float*)d_in[9];
    const float* Wn  = (const float*)d_in[10];
    const float* We  = (const float*)d_in[11];
    const float* bg  = (const float*)d_in[12];
    const float* Wc1 = (const float*)d_in[13];
    const float* bc1 = (const float*)d_in[14];
    const float* Wc2 = (const float*)d_in[15];
    const float* bc2 = (const float*)d_in[16];
    float* out = (float*)d_out;

    void* poff = nullptr;
    cudaGetSymbolAddress(&poff, g_off);

    // side stream + events, created once on the first (non-captured) call
    static cudaStream_t s2 = nullptr;
    static cudaEvent_t ev0 = nullptr, ev1 = nullptr, ev2 = nullptr;
    if (!s2){
        cudaStreamCreateWithFlags(&s2, cudaStreamNonBlocking);
        cudaEventCreateWithFlags(&ev0, cudaEventDisableTiming);
        cudaEventCreateWithFlags(&ev1, cudaEventDisableTiming);
        cudaEventCreateWithFlags(&ev2, cudaEventDisableTiming);
    }

    // fork: dense chain on s2, overlapped with CSR build on default stream
    cudaEventRecord(ev0, 0);
    cudaStreamWaitEvent(s2, ev0, 0);
    k_gemm1<<<196, 256, 0, s2>>>(x, W1, b1);
    cudaEventRecord(ev1, s2);
    k_ew1<<<8, 128, 0, s2>>>(ef, We);
    k_ew2<<<8, 128, 0, s2>>>(adj);
    cudaEventRecord(ev2, s2);

    // CSR build (default stream)
    cudaMemsetAsync(poff, 0, (N_NODES+1)*sizeof(int));
    k_count<<<3907, 256>>>(ei);
    k_scan1<<<SCAN_BLOCKS, 1024>>>();
    k_scan2<<<1, 64>>>();
    k_scan3<<<SCAN_BLOCKS, 1024>>>();
    k_fill<<<3907, 256>>>(ei, ew);

    // join gemm1 before gather1
    cudaStreamWaitEvent(0, ev1, 0);
    k_gather1<<<6250, 256>>>(W2, b2);
    k_gather2<<<6250, 256>>>();
    k_gather3<<<6250, 256>>>();

    // join ew2 before final
    cudaStreamWaitEvent(0, ev2, 0);
    k_final<<<391, 128>>>(T, Wn, bg, Wc1, bc1, Wc2, bc2, out);
}